// round 11
// baseline (speedup 1.0000x reference)
#include <cuda_runtime.h>
#include <cstdint>

// out[i][j] = -sqrt(max(||f_i||^2 + ||f_j||^2 - 2 f_i.f_j, 0)),  f: [8192,512] fp32
// int8 IMMA syrk (2x bf16 MAC rate, exact s32 accumulation):
//   per-row symmetric quantization q_i = round(f_i * 127/max|f_i|), exact fp32
//   norms, gram_ij ~= s_i s_j <q_i, q_j>.  Upper-triangular CTA tiles only,
//   mirror via transposed SMEM staging + float4 stores. mma.sync m16n8k32
//   s8s8s32, CTA tile 128x128, 4 warps (2x2), warp tile 64x64, BK=128 bytes,
//   3-stage cp.async pipeline, register double-buffered ldmatrix/mma,
//   2 CTAs/SM. Diagonal forced to 0.

#define NROWS 8192
#define DDIM  512

#define TM 128
#define TN 128
#define BKB 128                    // K-bytes per tile (128 int8)
#define LDB 144                    // smem row stride bytes (128 + 16): conflict-free
#define STAGES 3
#define NKT (DDIM / BKB)           // 4
#define NT (NROWS / TM)            // 64
#define NTILES (NT * (NT + 1) / 2) // 2080

#define A_BYT (TM * LDB)           // 18432 B per stage
#define B_BYT (TN * LDB)
#define PIPE_BYTES (STAGES * (A_BYT + B_BYT))        // 110592 B
#define STG_S 132                  // transposed-stage stride (floats)
#define SMEM_BYTES (PIPE_BYTES + TN * 8)             // + col norms + col scales

__device__ uint8_t g_q[NROWS * DDIM];
__device__ float g_norms[NROWS];
__device__ float g_scale[NROWS];   // dequant scale s_i = max|row|/127

// ---------------------------------------------------------------------------
// Prep: warp per row. Pass 1: load 16 floats/lane (coalesced float4), exact
// fp32 sumsq + max|.| reductions. Pass 2: quantize to int8, coalesced u32 store.
// ---------------------------------------------------------------------------
__global__ __launch_bounds__(256)
void prep_kernel(const float* __restrict__ f) {
    const int lane = threadIdx.x & 31;
    const int row  = blockIdx.x * 8 + (threadIdx.x >> 5);
    const float* src = f + (size_t)row * DDIM;

    float4 v[4];
    float ss = 0.f, mx = 0.f;
#pragma unroll
    for (int i = 0; i < 4; i++) {
        v[i] = *(const float4*)(src + lane * 4 + i * 128);
        ss += v[i].x * v[i].x + v[i].y * v[i].y + v[i].z * v[i].z + v[i].w * v[i].w;
        mx = fmaxf(mx, fmaxf(fmaxf(fabsf(v[i].x), fabsf(v[i].y)),
                             fmaxf(fabsf(v[i].z), fabsf(v[i].w))));
    }
#pragma unroll
    for (int o = 16; o; o >>= 1) {
        ss += __shfl_xor_sync(0xffffffffu, ss, o);
        mx = fmaxf(mx, __shfl_xor_sync(0xffffffffu, mx, o));
    }
    mx = fmaxf(mx, 1e-20f);
    const float inv = 127.f / mx;

    uint32_t* dst = (uint32_t*)(g_q + (size_t)row * DDIM);
#pragma unroll
    for (int i = 0; i < 4; i++) {
        int b0 = __float2int_rn(v[i].x * inv);
        int b1 = __float2int_rn(v[i].y * inv);
        int b2 = __float2int_rn(v[i].z * inv);
        int b3 = __float2int_rn(v[i].w * inv);
        uint32_t pk = (uint32_t)(b0 & 0xFF) | ((uint32_t)(b1 & 0xFF) << 8) |
                      ((uint32_t)(b2 & 0xFF) << 16) | ((uint32_t)(b3 & 0xFF) << 24);
        dst[lane + i * 32] = pk;
    }
    if (lane == 0) {
        g_norms[row] = ss;
        g_scale[row] = mx / 127.f;
    }
}

// ---------------------------------------------------------------------------
__device__ __forceinline__ int tri_offset(int bi) {
    return bi * (2 * NT - bi + 1) / 2;
}

__global__ __launch_bounds__(128, 2)
void gemm_kernel(float* __restrict__ out) {
    extern __shared__ uint8_t sm[];
    uint8_t* As = sm;                       // [STAGES][TM][LDB]
    uint8_t* Bs = sm + STAGES * A_BYT;      // [STAGES][TN][LDB]
    float* nb_s = reinterpret_cast<float*>(sm + PIPE_BYTES);        // [TN]
    float* sb_s = nb_s + TN;                                        // [TN]
    float* staged = reinterpret_cast<float*>(sm);   // [TN][STG_S] (reuses pipe)

    const int tid  = threadIdx.x;
    const int lane = tid & 31;
    const int warp = tid >> 5;
    const int wm = warp >> 1;   // 0..1 -> 64 rows
    const int wn = warp & 1;    // 0..1 -> 64 cols

    // decode upper-triangular tile index: t -> (bi, bj), bj >= bi
    const int t = blockIdx.x;
    int bi = (int)(((2.f * NT + 1.f) -
                    sqrtf((2.f * NT + 1.f) * (2.f * NT + 1.f) - 8.f * (float)t)) * 0.5f);
    while (bi > 0 && tri_offset(bi) > t) bi--;
    while (tri_offset(bi + 1) <= t) bi++;
    const int bj = bi + (t - tri_offset(bi));

    const int rowA0 = bi * TM;
    const int rowB0 = bj * TN;

    if (tid < TN) {
        nb_s[tid] = g_norms[rowB0 + tid];
        sb_s[tid] = g_scale[rowB0 + tid];
    }

    int acc[4][8][4];
#pragma unroll
    for (int i = 0; i < 4; i++)
#pragma unroll
        for (int j = 0; j < 8; j++)
#pragma unroll
            for (int r = 0; r < 4; r++) acc[i][j][r] = 0;

    // ldmatrix thread mapping (b16 view: 16x16 b16 tile == 16x32 s8 tile)
    const int a_row = wm * 64 + (lane & 7) + ((lane >> 3) & 1) * 8;  // + mt*16
    const int a_kb  = (lane >> 4) * 16;                              // byte col, + ks*32
    const int b_row = wn * 64 + (lane & 7) + (lane >> 4) * 8;        // + p*16
    const int b_kb  = ((lane >> 3) & 1) * 16;                        // byte col, + ks*32

#define ISSUE(kt_, s_)                                                                        \
    do {                                                                                      \
        const int k0_ = (kt_) * BKB;                                                          \
        uint8_t* as_ = As + (s_) * A_BYT;                                                     \
        uint8_t* bs_ = Bs + (s_) * B_BYT;                                                     \
        _Pragma("unroll")                                                                     \
        for (int i_ = 0; i_ < 8; i_++) {                                                      \
            int idx_ = tid + i_ * 128;                                                        \
            int r_   = idx_ >> 3;                                                             \
            int c_   = (idx_ & 7) << 4;                                                       \
            uint32_t da_ = (uint32_t)__cvta_generic_to_shared(as_ + r_ * LDB + c_);           \
            const uint8_t* ga_ = g_q + (size_t)(rowA0 + r_) * DDIM + k0_ + c_;                \
            asm volatile("cp.async.cg.shared.global [%0], [%1], 16;\n" :: "r"(da_), "l"(ga_));\
            uint32_t db_ = (uint32_t)__cvta_generic_to_shared(bs_ + r_ * LDB + c_);           \
            const uint8_t* gb_ = g_q + (size_t)(rowB0 + r_) * DDIM + k0_ + c_;                \
            asm volatile("cp.async.cg.shared.global [%0], [%1], 16;\n" :: "r"(db_), "l"(gb_));\
        }                                                                                     \
        asm volatile("cp.async.commit_group;\n" ::: "memory");                                \
    } while (0)

#define LOAD_FRAGS(as_, bs_, ks_, fb_)                                                        \
    do {                                                                                      \
        _Pragma("unroll")                                                                     \
        for (int mt_ = 0; mt_ < 4; mt_++) {                                                   \
            uint32_t ad_ = (uint32_t)__cvta_generic_to_shared(                                \
                (as_) + (a_row + mt_ * 16) * LDB + (ks_) * 32 + a_kb);                        \
            asm volatile(                                                                     \
                "ldmatrix.sync.aligned.m8n8.x4.shared.b16 {%0,%1,%2,%3}, [%4];\n"             \
                : "=r"(a[fb_][mt_][0]), "=r"(a[fb_][mt_][1]),                                 \
                  "=r"(a[fb_][mt_][2]), "=r"(a[fb_][mt_][3])                                  \
                : "r"(ad_));                                                                  \
        }                                                                                     \
        _Pragma("unroll")                                                                     \
        for (int p_ = 0; p_ < 4; p_++) {                                                      \
            uint32_t bd_ = (uint32_t)__cvta_generic_to_shared(                                \
                (bs_) + (b_row + p_ * 16) * LDB + (ks_) * 32 + b_kb);                         \
            asm volatile(                                                                     \
                "ldmatrix.sync.aligned.m8n8.x4.shared.b16 {%0,%1,%2,%3}, [%4];\n"             \
                : "=r"(b[fb_][2 * p_][0]), "=r"(b[fb_][2 * p_][1]),                           \
                  "=r"(b[fb_][2 * p_ + 1][0]), "=r"(b[fb_][2 * p_ + 1][1])                    \
                : "r"(bd_));                                                                  \
        }                                                                                     \
    } while (0)

#define MMA_STEP(fb_)                                                                         \
    do {                                                                                      \
        _Pragma("unroll")                                                                     \
        for (int mt_ = 0; mt_ < 4; mt_++) {                                                   \
            _Pragma("unroll")                                                                 \
            for (int nt_ = 0; nt_ < 8; nt_++) {                                               \
                asm volatile(                                                                 \
                    "mma.sync.aligned.m16n8k32.row.col.s32.s8.s8.s32 "                        \
                    "{%0,%1,%2,%3}, {%4,%5,%6,%7}, {%8,%9}, {%0,%1,%2,%3};\n"                 \
                    : "+r"(acc[mt_][nt_][0]), "+r"(acc[mt_][nt_][1]),                         \
                      "+r"(acc[mt_][nt_][2]), "+r"(acc[mt_][nt_][3])                          \
                    : "r"(a[fb_][mt_][0]), "r"(a[fb_][mt_][1]),                               \
                      "r"(a[fb_][mt_][2]), "r"(a[fb_][mt_][3]),                               \
                      "r"(b[fb_][nt_][0]), "r"(b[fb_][nt_][1]));                              \
            }                                                                                 \
        }                                                                                     \
    } while (0)

    uint32_t a[2][4][4];
    uint32_t b[2][8][2];

    ISSUE(0, 0);
    ISSUE(1, 1);

    for (int kt = 0; kt < NKT; kt++) {
        if (kt < NKT - 1)
            asm volatile("cp.async.wait_group 1;" ::: "memory");
        else
            asm volatile("cp.async.wait_group 0;" ::: "memory");
        __syncthreads();

        if (kt + 2 < NKT) ISSUE(kt + 2, (kt + 2) % STAGES);

        const uint8_t* as = As + (kt % STAGES) * A_BYT;
        const uint8_t* bs = Bs + (kt % STAGES) * B_BYT;

        // 4 k32 sub-steps per kt, register double-buffered
        LOAD_FRAGS(as, bs, 0, 0);
#pragma unroll
        for (int ks = 0; ks < 4; ks++) {
            if (ks < 3) LOAD_FRAGS(as, bs, ks + 1, (ks + 1) & 1);
            MMA_STEP(ks & 1);
        }
    }

    // ---- epilogue ---------------------------------------------------------
    const bool mirror = (bi != bj);
    __syncthreads();   // pipeline smem now reusable as staged[]

#pragma unroll
    for (int mt = 0; mt < 4; mt++) {
        int rl0 = wm * 64 + mt * 16 + (lane >> 2);
        int rl1 = rl0 + 8;
        int r0 = rowA0 + rl0;
        int r1 = rowA0 + rl1;
        float na0 = g_norms[r0];
        float na1 = g_norms[r1];
        float sa0 = 2.f * g_scale[r0];
        float sa1 = 2.f * g_scale[r1];
#pragma unroll
        for (int nt = 0; nt < 8; nt++) {
            int cl = wn * 64 + nt * 8 + 2 * (lane & 3);
            int c0 = rowB0 + cl;
            int c1 = c0 + 1;
            float nb0 = nb_s[cl];
            float nb1 = nb_s[cl + 1];
            float sb0 = sb_s[cl];
            float sb1 = sb_s[cl + 1];

            float d00 = fmaxf(na0 + nb0 - sa0 * sb0 * (float)acc[mt][nt][0], 0.f);
            float d01 = fmaxf(na0 + nb1 - sa0 * sb1 * (float)acc[mt][nt][1], 0.f);
            float d10 = fmaxf(na1 + nb0 - sa1 * sb0 * (float)acc[mt][nt][2], 0.f);
            float d11 = fmaxf(na1 + nb1 - sa1 * sb1 * (float)acc[mt][nt][3], 0.f);

            float v00 = (r0 == c0) ? 0.f : -sqrtf(d00);
            float v01 = (r0 == c1) ? 0.f : -sqrtf(d01);
            float v10 = (r1 == c0) ? 0.f : -sqrtf(d10);
            float v11 = (r1 == c1) ? 0.f : -sqrtf(d11);

            *(float2*)&out[(size_t)r0 * NROWS + c0] = make_float2(v00, v01);
            *(float2*)&out[(size_t)r1 * NROWS + c0] = make_float2(v10, v11);

            if (mirror) {  // transposed staging: staged[cl][rl]
                staged[cl * STG_S + rl0]       = v00;
                staged[(cl + 1) * STG_S + rl0] = v01;
                staged[cl * STG_S + rl1]       = v10;
                staged[(cl + 1) * STG_S + rl1] = v11;
            }
        }
    }

    // mirror: out[rowB0+cl][rowA0 + 0..127], float4 coalesced
    if (mirror) {
        __syncthreads();
#pragma unroll
        for (int i = 0; i < 32; i++) {
            int cl = warp * 32 + i;
            float4 v = *(float4*)&staged[cl * STG_S + lane * 4];
            *(float4*)(out + (size_t)(rowB0 + cl) * NROWS + rowA0 + lane * 4) = v;
        }
    }
#undef ISSUE
#undef LOAD_FRAGS
#undef MMA_STEP
}

// ---------------------------------------------------------------------------
extern "C" void kernel_launch(void* const* d_in, const int* in_sizes, int n_in,
                              void* d_out, int out_size) {
    const float* f = (const float*)d_in[0];
    float* out = (float*)d_out;
    (void)in_sizes; (void)n_in; (void)out_size;

    cudaFuncSetAttribute(gemm_kernel, cudaFuncAttributeMaxDynamicSharedMemorySize, SMEM_BYTES);

    prep_kernel<<<NROWS / 8, 256>>>(f);
    gemm_kernel<<<NTILES, 128, SMEM_BYTES>>>(out);
}

// round 12
// speedup vs baseline: 1.6070x; 1.6070x over previous
#include <cuda_runtime.h>
#include <cuda_bf16.h>
#include <cstdint>

// out[i][j] = -sqrt(max(||f_i||^2 + ||f_j||^2 - 2 f_i.f_j, 0)),  f: [8192,512] fp32
// bf16 mma.sync m16n8k16 syrk, upper-triangular tiles + mirrored write.
// PERSISTENT kernel (grid = 296 = 2 CTAs x 148 SMs) with CROSS-TILE software
// pipelining: cp.async 3-stage rotation continues across tile boundaries
// (stage base += NKT mod 3 per tile), so the pipe never drains. Mirror staging
// lives in the two pipe-stage blocks that are free during the epilogue.
// CTA tile 128x128, 4 warps (2x2), warp tile 64x64, BK=64, diag = 0.

#define NROWS 8192
#define DDIM  512

#define TM 128
#define TN 128
#define BK 64
#define LDSZ 72                    // bf16 elems per smem row (144 B), conflict-free
#define NKT (DDIM / BK)            // 8
#define NT (NROWS / TM)            // 64
#define NTILES (NT * (NT + 1) / 2) // 2080
#define GRID 296                   // 148 SMs x 2 CTAs resident

#define A_BYTES (TM * LDSZ * 2)    // 18432 B
#define STG_BYTES (2 * A_BYTES)    // 36864 B per stage block [A|B]
#define PIPE_BYTES (3 * STG_BYTES) // 110592 B
#define STG_S 132                  // staged stride (floats); 64x132x4 = 33792 <= 36864
#define SMEM_BYTES (PIPE_BYTES + TN * 4)

__device__ __nv_bfloat16 g_fb[NROWS * DDIM];
__device__ float g_norms[NROWS];

// ---------------------------------------------------------------------------
__global__ __launch_bounds__(256)
void prep_kernel(const float* __restrict__ f) {
    const int lane = threadIdx.x & 31;
    const int row  = blockIdx.x * 8 + (threadIdx.x >> 5);
    const float* src = f + (size_t)row * DDIM;
    __nv_bfloat16* dst = g_fb + (size_t)row * DDIM;

    float s = 0.f;
#pragma unroll
    for (int half = 0; half < 2; half++) {
        const float4 v0 = *(const float4*)(src + half * 256 + lane * 8);
        const float4 v1 = *(const float4*)(src + half * 256 + lane * 8 + 4);
        s += v0.x * v0.x + v0.y * v0.y + v0.z * v0.z + v0.w * v0.w;
        s += v1.x * v1.x + v1.y * v1.y + v1.z * v1.z + v1.w * v1.w;
        __nv_bfloat162 p0 = __float22bfloat162_rn(make_float2(v0.x, v0.y));
        __nv_bfloat162 p1 = __float22bfloat162_rn(make_float2(v0.z, v0.w));
        __nv_bfloat162 p2 = __float22bfloat162_rn(make_float2(v1.x, v1.y));
        __nv_bfloat162 p3 = __float22bfloat162_rn(make_float2(v1.z, v1.w));
        uint4 pk;
        pk.x = *(uint32_t*)&p0; pk.y = *(uint32_t*)&p1;
        pk.z = *(uint32_t*)&p2; pk.w = *(uint32_t*)&p3;
        *(uint4*)(dst + half * 256 + lane * 8) = pk;
    }
#pragma unroll
    for (int o = 16; o; o >>= 1) s += __shfl_xor_sync(0xffffffffu, s, o);
    if (lane == 0) g_norms[row] = s;
}

// ---------------------------------------------------------------------------
__device__ __forceinline__ int tri_offset(int bi) {
    return bi * (2 * NT - bi + 1) / 2;
}
__device__ __forceinline__ void decode_tile(int t, int& bi, int& bj) {
    int x = (int)(((2.f * NT + 1.f) -
                   sqrtf((2.f * NT + 1.f) * (2.f * NT + 1.f) - 8.f * (float)t)) * 0.5f);
    while (x > 0 && tri_offset(x) > t) x--;
    while (tri_offset(x + 1) <= t) x++;
    bi = x;
    bj = x + (t - tri_offset(x));
}

__global__ __launch_bounds__(128, 2)
void gemm_kernel(float* __restrict__ out) {
    extern __shared__ uint8_t smb[];
    float* nb_s = reinterpret_cast<float*>(smb + PIPE_BYTES);   // [TN]

    const int tid  = threadIdx.x;
    const int lane = tid & 31;
    const int warp = tid >> 5;
    const int wm = warp >> 1;
    const int wn = warp & 1;

    const int a_row = wm * 64 + (lane & 7) + ((lane >> 3) & 1) * 8;  // + mt*16
    const int a_kk  = (lane >> 4) * 8;                               // + ks*16
    const int b_row = wn * 64 + (lane & 7) + (lane >> 4) * 8;        // + p*16
    const int b_kk  = ((lane >> 3) & 1) * 8;                         // + ks*16

    uint32_t a[2][4][4];
    uint32_t b[2][8][2];

    // issue one K-tile into stage block s_ for tile rows (rA_, rB_)
#define ISSUE(rA_, rB_, kt_, s_)                                                             \
    do {                                                                                      \
        const int k0_ = (kt_) * BK;                                                           \
        __nv_bfloat16* as_ = (__nv_bfloat16*)(smb + (s_) * STG_BYTES);                        \
        __nv_bfloat16* bs_ = (__nv_bfloat16*)(smb + (s_) * STG_BYTES + A_BYTES);              \
        _Pragma("unroll")                                                                     \
        for (int i_ = 0; i_ < 8; i_++) {                                                      \
            int idx_ = tid + i_ * 128;                                                        \
            int r_   = idx_ >> 3;                                                             \
            int c_   = (idx_ & 7) << 3;                                                       \
            uint32_t da_ = (uint32_t)__cvta_generic_to_shared(as_ + r_ * LDSZ + c_);          \
            const __nv_bfloat16* ga_ = g_fb + (size_t)((rA_) + r_) * DDIM + k0_ + c_;         \
            asm volatile("cp.async.cg.shared.global [%0], [%1], 16;\n" :: "r"(da_), "l"(ga_));\
            uint32_t db_ = (uint32_t)__cvta_generic_to_shared(bs_ + r_ * LDSZ + c_);          \
            const __nv_bfloat16* gb_ = g_fb + (size_t)((rB_) + r_) * DDIM + k0_ + c_;         \
            asm volatile("cp.async.cg.shared.global [%0], [%1], 16;\n" :: "r"(db_), "l"(gb_));\
        }                                                                                     \
        asm volatile("cp.async.commit_group;\n" ::: "memory");                                \
    } while (0)

#define LOAD_FRAGS(as_, bs_, ks_, fb_)                                                        \
    do {                                                                                      \
        _Pragma("unroll")                                                                     \
        for (int mt_ = 0; mt_ < 4; mt_++) {                                                   \
            uint32_t ad_ = (uint32_t)__cvta_generic_to_shared(                                \
                (as_) + (a_row + mt_ * 16) * LDSZ + (ks_) * 16 + a_kk);                       \
            asm volatile(                                                                     \
                "ldmatrix.sync.aligned.m8n8.x4.shared.b16 {%0,%1,%2,%3}, [%4];\n"             \
                : "=r"(a[fb_][mt_][0]), "=r"(a[fb_][mt_][1]),                                 \
                  "=r"(a[fb_][mt_][2]), "=r"(a[fb_][mt_][3])                                  \
                : "r"(ad_));                                                                  \
        }                                                                                     \
        _Pragma("unroll")                                                                     \
        for (int p_ = 0; p_ < 4; p_++) {                                                      \
            uint32_t bd_ = (uint32_t)__cvta_generic_to_shared(                                \
                (bs_) + (b_row + p_ * 16) * LDSZ + (ks_) * 16 + b_kk);                        \
            asm volatile(                                                                     \
                "ldmatrix.sync.aligned.m8n8.x4.shared.b16 {%0,%1,%2,%3}, [%4];\n"             \
                : "=r"(b[fb_][2 * p_][0]), "=r"(b[fb_][2 * p_][1]),                           \
                  "=r"(b[fb_][2 * p_ + 1][0]), "=r"(b[fb_][2 * p_ + 1][1])                    \
                : "r"(bd_));                                                                  \
        }                                                                                     \
    } while (0)

#define MMA_STEP(fb_)                                                                         \
    do {                                                                                      \
        _Pragma("unroll")                                                                     \
        for (int mt_ = 0; mt_ < 4; mt_++) {                                                   \
            _Pragma("unroll")                                                                 \
            for (int nt_ = 0; nt_ < 8; nt_++) {                                               \
                asm volatile(                                                                 \
                    "mma.sync.aligned.m16n8k16.row.col.f32.bf16.bf16.f32 "                    \
                    "{%0,%1,%2,%3}, {%4,%5,%6,%7}, {%8,%9}, {%0,%1,%2,%3};\n"                 \
                    : "+f"(acc[mt_][nt_][0]), "+f"(acc[mt_][nt_][1]),                         \
                      "+f"(acc[mt_][nt_][2]), "+f"(acc[mt_][nt_][3])                          \
                    : "r"(a[fb_][mt_][0]), "r"(a[fb_][mt_][1]),                               \
                      "r"(a[fb_][mt_][2]), "r"(a[fb_][mt_][3]),                               \
                      "r"(b[fb_][nt_][0]), "r"(b[fb_][nt_][1]));                              \
            }                                                                                 \
        }                                                                                     \
    } while (0)

    int t = blockIdx.x;
    int bi, bj;
    decode_tile(t, bi, bj);
    int rowA0 = bi * TM;
    int rowB0 = bj * TN;
    int sb = 0;   // stage block of kt=0 for current tile

    ISSUE(rowA0, rowB0, 0, 0);
    ISSUE(rowA0, rowB0, 1, 1);

    for (;;) {
        const bool has_next = (t + GRID) < NTILES;
        int nbi = 0, nbj = 0, nrowA0 = 0, nrowB0 = 0;
        if (has_next) {
            decode_tile(t + GRID, nbi, nbj);
            nrowA0 = nbi * TM;
            nrowB0 = nbj * TN;
        }

        if (tid < TN) nb_s[tid] = g_norms[rowB0 + tid];

        float acc[4][8][4];
#pragma unroll
        for (int i = 0; i < 4; i++)
#pragma unroll
            for (int j = 0; j < 8; j++)
#pragma unroll
                for (int r = 0; r < 4; r++) acc[i][j][r] = 0.f;

        int st = sb;  // stage of current kt
#pragma unroll
        for (int kt = 0; kt < NKT; kt++) {
            if (kt == NKT - 1 && !has_next)
                asm volatile("cp.async.wait_group 0;" ::: "memory");
            else
                asm volatile("cp.async.wait_group 1;" ::: "memory");
            __syncthreads();

            if (kt < NKT - 2) {
                int s2 = st + 2 >= 3 ? st - 1 : st + 2;
                ISSUE(rowA0, rowB0, kt + 2, s2);
            } else if (kt == NKT - 2 && has_next) {
                int s2 = st + 2 >= 3 ? st - 1 : st + 2;   // = (sb+8)%3
                ISSUE(nrowA0, nrowB0, 0, s2);
            }
            // kt == NKT-1: nothing (next tile kt=1 issued after epilogue)

            const __nv_bfloat16* as = (const __nv_bfloat16*)(smb + st * STG_BYTES);
            const __nv_bfloat16* bs = (const __nv_bfloat16*)(smb + st * STG_BYTES + A_BYTES);

            LOAD_FRAGS(as, bs, 0, 0);
#pragma unroll
            for (int ks = 0; ks < 4; ks++) {
                if (ks < 3) LOAD_FRAGS(as, bs, ks + 1, (ks + 1) & 1);
                MMA_STEP(ks & 1);
            }
            st = (st + 1 == 3) ? 0 : st + 1;
        }

        // ---- epilogue: staged[] lives in stage blocks sb and (sb+1)%3 ------
        // (in flight: next tile kt=0 in (sb+2)%3 only)
        const bool mirror = (bi != bj);
        const int sb1 = (sb + 1 == 3) ? 0 : sb + 1;
        float* stg_lo = (float*)(smb + sb * STG_BYTES);    // cl 0..63
        float* stg_hi = (float*)(smb + sb1 * STG_BYTES);   // cl 64..127
        float* stgw = wn ? stg_hi : stg_lo;                // this warp's col half
        __syncthreads();   // all warps done with kt=7 ldmatrix before staging

#pragma unroll
        for (int mt = 0; mt < 4; mt++) {
            int rl0 = wm * 64 + mt * 16 + (lane >> 2);
            int rl1 = rl0 + 8;
            int r0 = rowA0 + rl0;
            int r1 = rowA0 + rl1;
            float na0 = g_norms[r0];
            float na1 = g_norms[r1];
#pragma unroll
            for (int nt = 0; nt < 8; nt++) {
                int cl = wn * 64 + nt * 8 + 2 * (lane & 3);
                int cll = nt * 8 + 2 * (lane & 3);           // col within half
                int c0 = rowB0 + cl;
                int c1 = c0 + 1;
                float nb0 = nb_s[cl];
                float nb1 = nb_s[cl + 1];

                float d00 = fmaxf(na0 + nb0 - 2.f * acc[mt][nt][0], 0.f);
                float d01 = fmaxf(na0 + nb1 - 2.f * acc[mt][nt][1], 0.f);
                float d10 = fmaxf(na1 + nb0 - 2.f * acc[mt][nt][2], 0.f);
                float d11 = fmaxf(na1 + nb1 - 2.f * acc[mt][nt][3], 0.f);

                float v00 = (r0 == c0) ? 0.f : -sqrtf(d00);
                float v01 = (r0 == c1) ? 0.f : -sqrtf(d01);
                float v10 = (r1 == c0) ? 0.f : -sqrtf(d10);
                float v11 = (r1 == c1) ? 0.f : -sqrtf(d11);

                *(float2*)&out[(size_t)r0 * NROWS + c0] = make_float2(v00, v01);
                *(float2*)&out[(size_t)r1 * NROWS + c0] = make_float2(v10, v11);

                if (mirror) {  // transposed staging: staged[cl][rl]
                    stgw[cll * STG_S + rl0]       = v00;
                    stgw[(cll + 1) * STG_S + rl0] = v01;
                    stgw[cll * STG_S + rl1]       = v10;
                    stgw[(cll + 1) * STG_S + rl1] = v11;
                }
            }
        }

        if (mirror) {
            __syncthreads();
            float* stgr = (warp >= 2) ? stg_hi : stg_lo;
#pragma unroll
            for (int i = 0; i < 32; i++) {
                int cl = warp * 32 + i;
                float4 v = *(float4*)&stgr[(cl & 63) * STG_S + lane * 4];
                *(float4*)(out + (size_t)(rowB0 + cl) * NROWS + rowA0 + lane * 4) = v;
            }
        }

        if (!has_next) break;

        __syncthreads();   // staged reads complete before next kt=1 overwrites block sb
        ISSUE(nrowA0, nrowB0, 1, sb);   // next tile kt=1 -> stage (sb+9)%3 == sb

        t += GRID;
        bi = nbi; bj = nbj; rowA0 = nrowA0; rowB0 = nrowB0;
        sb = (sb + 2 >= 3) ? sb - 1 : sb + 2;   // (sb + NKT) % 3
    }
#undef ISSUE
#undef LOAD_FRAGS
#undef MMA_STEP
}

// ---------------------------------------------------------------------------
extern "C" void kernel_launch(void* const* d_in, const int* in_sizes, int n_in,
                              void* d_out, int out_size) {
    const float* f = (const float*)d_in[0];
    float* out = (float*)d_out;
    (void)in_sizes; (void)n_in; (void)out_size;

    cudaFuncSetAttribute(gemm_kernel, cudaFuncAttributeMaxDynamicSharedMemorySize, SMEM_BYTES);

    prep_kernel<<<NROWS / 8, 256>>>(f);
    gemm_kernel<<<GRID, 128, SMEM_BYTES>>>(out);
}

// round 13
// speedup vs baseline: 1.8736x; 1.1659x over previous
#include <cuda_runtime.h>
#include <cuda_bf16.h>
#include <cstdint>

// out[i][j] = -sqrt(max(||f_i||^2 + ||f_j||^2 - 2 f_i.f_j, 0)),  f: [8192,512] fp32
// bf16 mma.sync m16n8k16 syrk, upper-triangular CTA tiles + mirrored write.
// CTA tile 128x128, 4 warps (2x2), warp tile 64x64, BK=64, 3-stage cp.async
// pipeline, 2 CTAs/SM. CROSS-KT FRAGMENT PREFETCH: the per-kt barrier sits in
// ks=3 of the previous iteration, immediately followed by prefetching the next
// K-tile's first fragments, so every iteration starts MMA-ready (no post-
// barrier ldmatrix bubble). Diagonal tiles (no mirror) mapped last. Diag = 0.

#define NROWS 8192
#define DDIM  512

#define TM 128
#define TN 128
#define BK 64
#define LDSZ 72                    // 64 + 8 bf16 pad -> 144B row stride, conflict-free
#define STAGES 3
#define NKT (DDIM / BK)            // 8
#define NT (NROWS / TM)            // 64
#define NSTRICT (NT * (NT - 1) / 2)   // 2016 strictly-upper tiles
#define NTILES (NSTRICT + NT)         // + 64 diagonal tiles = 2080

#define A_ELE (TM * LDSZ)          // 9216 bf16 per stage
#define B_ELE (TN * LDSZ)
#define PIPE_BYTES (STAGES * (A_ELE + B_ELE) * 2)    // 110592 B
#define STG_S 132                  // transposed-stage stride (floats)
#define SMEM_BYTES (PIPE_BYTES + TN * 4)

__device__ __nv_bfloat16 g_fb[NROWS * DDIM];
__device__ float g_norms[NROWS];

// ---------------------------------------------------------------------------
__global__ __launch_bounds__(256)
void prep_kernel(const float* __restrict__ f) {
    const int lane = threadIdx.x & 31;
    const int row  = blockIdx.x * 8 + (threadIdx.x >> 5);
    const float* src = f + (size_t)row * DDIM;
    __nv_bfloat16* dst = g_fb + (size_t)row * DDIM;

    float s = 0.f;
#pragma unroll
    for (int half = 0; half < 2; half++) {
        const float4 v0 = *(const float4*)(src + half * 256 + lane * 8);
        const float4 v1 = *(const float4*)(src + half * 256 + lane * 8 + 4);
        s += v0.x * v0.x + v0.y * v0.y + v0.z * v0.z + v0.w * v0.w;
        s += v1.x * v1.x + v1.y * v1.y + v1.z * v1.z + v1.w * v1.w;
        __nv_bfloat162 p0 = __float22bfloat162_rn(make_float2(v0.x, v0.y));
        __nv_bfloat162 p1 = __float22bfloat162_rn(make_float2(v0.z, v0.w));
        __nv_bfloat162 p2 = __float22bfloat162_rn(make_float2(v1.x, v1.y));
        __nv_bfloat162 p3 = __float22bfloat162_rn(make_float2(v1.z, v1.w));
        uint4 pk;
        pk.x = *(uint32_t*)&p0; pk.y = *(uint32_t*)&p1;
        pk.z = *(uint32_t*)&p2; pk.w = *(uint32_t*)&p3;
        *(uint4*)(dst + half * 256 + lane * 8) = pk;
    }
#pragma unroll
    for (int o = 16; o; o >>= 1) s += __shfl_xor_sync(0xffffffffu, s, o);
    if (lane == 0) g_norms[row] = s;
}

// ---------------------------------------------------------------------------
// strictly-upper tile offset: number of tiles with first index < x
__device__ __forceinline__ int s_off(int x) { return x * (2 * NT - 1 - x) / 2; }

__global__ __launch_bounds__(128, 2)
void gemm_kernel(float* __restrict__ out) {
    extern __shared__ __nv_bfloat16 sm[];
    __nv_bfloat16* As = sm;                     // [STAGES][TM][LDSZ]
    __nv_bfloat16* Bs = sm + STAGES * A_ELE;    // [STAGES][TN][LDSZ]
    float* nb_s = reinterpret_cast<float*>(sm + STAGES * (A_ELE + B_ELE)); // [TN]
    float* staged = reinterpret_cast<float*>(sm);       // [TN][STG_S] (reuses pipe)

    const int tid  = threadIdx.x;
    const int lane = tid & 31;
    const int warp = tid >> 5;
    const int wm = warp >> 1;
    const int wn = warp & 1;

    // tile decode: strictly-upper tiles first, diagonal tiles last
    const int t = blockIdx.x;
    int bi, bj;
    if (t < NSTRICT) {
        bi = (int)(((2.f * NT - 1.f) -
                    sqrtf((2.f * NT - 1.f) * (2.f * NT - 1.f) - 8.f * (float)t)) * 0.5f);
        while (bi > 0 && s_off(bi) > t) bi--;
        while (s_off(bi + 1) <= t) bi++;
        bj = bi + 1 + (t - s_off(bi));
    } else {
        bi = bj = t - NSTRICT;
    }

    const int rowA0 = bi * TM;
    const int rowB0 = bj * TN;

    if (tid < TN) nb_s[tid] = g_norms[rowB0 + tid];

    float acc[4][8][4];
#pragma unroll
    for (int i = 0; i < 4; i++)
#pragma unroll
        for (int j = 0; j < 8; j++)
#pragma unroll
            for (int r = 0; r < 4; r++) acc[i][j][r] = 0.f;

    const int a_row = wm * 64 + (lane & 7) + ((lane >> 3) & 1) * 8;  // + mt*16
    const int a_kk  = (lane >> 4) * 8;                               // + ks*16
    const int b_row = wn * 64 + (lane & 7) + (lane >> 4) * 8;        // + p*16
    const int b_kk  = ((lane >> 3) & 1) * 8;                         // + ks*16

#define ISSUE(kt_, s_)                                                                        \
    do {                                                                                      \
        const int k0_ = (kt_) * BK;                                                           \
        __nv_bfloat16* as_ = As + (s_) * A_ELE;                                               \
        __nv_bfloat16* bs_ = Bs + (s_) * B_ELE;                                               \
        _Pragma("unroll")                                                                     \
        for (int i_ = 0; i_ < 8; i_++) {                                                      \
            int idx_ = tid + i_ * 128;                                                        \
            int r_   = idx_ >> 3;                                                             \
            int c_   = (idx_ & 7) << 3;                                                       \
            uint32_t da_ = (uint32_t)__cvta_generic_to_shared(as_ + r_ * LDSZ + c_);          \
            const __nv_bfloat16* ga_ = g_fb + (size_t)(rowA0 + r_) * DDIM + k0_ + c_;         \
            asm volatile("cp.async.cg.shared.global [%0], [%1], 16;\n" :: "r"(da_), "l"(ga_));\
            uint32_t db_ = (uint32_t)__cvta_generic_to_shared(bs_ + r_ * LDSZ + c_);          \
            const __nv_bfloat16* gb_ = g_fb + (size_t)(rowB0 + r_) * DDIM + k0_ + c_;         \
            asm volatile("cp.async.cg.shared.global [%0], [%1], 16;\n" :: "r"(db_), "l"(gb_));\
        }                                                                                     \
        asm volatile("cp.async.commit_group;\n" ::: "memory");                                \
    } while (0)

#define LOAD_FRAGS(as_, bs_, ks_, fb_)                                                        \
    do {                                                                                      \
        _Pragma("unroll")                                                                     \
        for (int mt_ = 0; mt_ < 4; mt_++) {                                                   \
            uint32_t ad_ = (uint32_t)__cvta_generic_to_shared(                                \
                (as_) + (a_row + mt_ * 16) * LDSZ + (ks_) * 16 + a_kk);                       \
            asm volatile(                                                                     \
                "ldmatrix.sync.aligned.m8n8.x4.shared.b16 {%0,%1,%2,%3}, [%4];\n"             \
                : "=r"(a[fb_][mt_][0]), "=r"(a[fb_][mt_][1]),                                 \
                  "=r"(a[fb_][mt_][2]), "=r"(a[fb_][mt_][3])                                  \
                : "r"(ad_));                                                                  \
        }                                                                                     \
        _Pragma("unroll")                                                                     \
        for (int p_ = 0; p_ < 4; p_++) {                                                      \
            uint32_t bd_ = (uint32_t)__cvta_generic_to_shared(                                \
                (bs_) + (b_row + p_ * 16) * LDSZ + (ks_) * 16 + b_kk);                        \
            asm volatile(                                                                     \
                "ldmatrix.sync.aligned.m8n8.x4.shared.b16 {%0,%1,%2,%3}, [%4];\n"             \
                : "=r"(b[fb_][2 * p_][0]), "=r"(b[fb_][2 * p_][1]),                           \
                  "=r"(b[fb_][2 * p_ + 1][0]), "=r"(b[fb_][2 * p_ + 1][1])                    \
                : "r"(bd_));                                                                  \
        }                                                                                     \
    } while (0)

#define MMA_STEP(fb_)                                                                         \
    do {                                                                                      \
        _Pragma("unroll")                                                                     \
        for (int mt_ = 0; mt_ < 4; mt_++) {                                                   \
            _Pragma("unroll")                                                                 \
            for (int nt_ = 0; nt_ < 8; nt_++) {                                               \
                asm volatile(                                                                 \
                    "mma.sync.aligned.m16n8k16.row.col.f32.bf16.bf16.f32 "                    \
                    "{%0,%1,%2,%3}, {%4,%5,%6,%7}, {%8,%9}, {%0,%1,%2,%3};\n"                 \
                    : "+f"(acc[mt_][nt_][0]), "+f"(acc[mt_][nt_][1]),                         \
                      "+f"(acc[mt_][nt_][2]), "+f"(acc[mt_][nt_][3])                          \
                    : "r"(a[fb_][mt_][0]), "r"(a[fb_][mt_][1]),                               \
                      "r"(a[fb_][mt_][2]), "r"(a[fb_][mt_][3]),                               \
                      "r"(b[fb_][nt_][0]), "r"(b[fb_][nt_][1]));                              \
            }                                                                                 \
        }                                                                                     \
    } while (0)

    uint32_t a[2][4][4];
    uint32_t b[2][8][2];

    // prologue: stage 0 ready + first fragments preloaded
    ISSUE(0, 0);
    ISSUE(1, 1);
    asm volatile("cp.async.wait_group 1;" ::: "memory");   // group 0 complete
    __syncthreads();
    {
        const __nv_bfloat16* as0 = As;
        const __nv_bfloat16* bs0 = Bs;
        LOAD_FRAGS(as0, bs0, 0, 0);
    }

    int st = 0;
    for (int kt = 0; kt < NKT; kt++) {
        if (kt + 2 < NKT) {
            int s2 = (st + 2 >= 3) ? st - 1 : st + 2;
            ISSUE(kt + 2, s2);
        }
        const __nv_bfloat16* as = As + st * A_ELE;
        const __nv_bfloat16* bs = Bs + st * B_ELE;
        const int stn = (st + 1 == 3) ? 0 : st + 1;

        // ks=0..2: prefetch next sub-step during MMAs
        LOAD_FRAGS(as, bs, 1, 1);
        MMA_STEP(0);
        LOAD_FRAGS(as, bs, 2, 0);
        MMA_STEP(1);
        LOAD_FRAGS(as, bs, 3, 1);
        MMA_STEP(0);
        // ks=3: barrier for next stage + prefetch next kt's first fragments,
        // both hidden under the final MMA batch
        if (kt + 1 < NKT) {
            if (kt + 2 < NKT)
                asm volatile("cp.async.wait_group 1;" ::: "memory");
            else
                asm volatile("cp.async.wait_group 0;" ::: "memory");
            __syncthreads();
            const __nv_bfloat16* asn = As + stn * A_ELE;
            const __nv_bfloat16* bsn = Bs + stn * B_ELE;
            LOAD_FRAGS(asn, bsn, 0, 0);
        }
        MMA_STEP(1);
        st = stn;
    }

    // ---- epilogue ---------------------------------------------------------
    const bool mirror = (bi != bj);
    __syncthreads();   // all warps done with last ldmatrix; pipe smem reusable

#pragma unroll
    for (int mt = 0; mt < 4; mt++) {
        int rl0 = wm * 64 + mt * 16 + (lane >> 2);
        int rl1 = rl0 + 8;
        int r0 = rowA0 + rl0;
        int r1 = rowA0 + rl1;
        float na0 = g_norms[r0];
        float na1 = g_norms[r1];
#pragma unroll
        for (int nt = 0; nt < 8; nt++) {
            int cl = wn * 64 + nt * 8 + 2 * (lane & 3);
            int c0 = rowB0 + cl;
            int c1 = c0 + 1;
            float nb0 = nb_s[cl];
            float nb1 = nb_s[cl + 1];

            float d00 = fmaxf(na0 + nb0 - 2.f * acc[mt][nt][0], 0.f);
            float d01 = fmaxf(na0 + nb1 - 2.f * acc[mt][nt][1], 0.f);
            float d10 = fmaxf(na1 + nb0 - 2.f * acc[mt][nt][2], 0.f);
            float d11 = fmaxf(na1 + nb1 - 2.f * acc[mt][nt][3], 0.f);

            float v00 = (r0 == c0) ? 0.f : -sqrtf(d00);
            float v01 = (r0 == c1) ? 0.f : -sqrtf(d01);
            float v10 = (r1 == c0) ? 0.f : -sqrtf(d10);
            float v11 = (r1 == c1) ? 0.f : -sqrtf(d11);

            *(float2*)&out[(size_t)r0 * NROWS + c0] = make_float2(v00, v01);
            *(float2*)&out[(size_t)r1 * NROWS + c0] = make_float2(v10, v11);

            if (mirror) {  // transposed staging: staged[cl][rl]
                staged[cl * STG_S + rl0]       = v00;
                staged[(cl + 1) * STG_S + rl0] = v01;
                staged[cl * STG_S + rl1]       = v10;
                staged[(cl + 1) * STG_S + rl1] = v11;
            }
        }
    }

    // mirror: out[rowB0+cl][rowA0 + 0..127], float4 coalesced
    if (mirror) {
        __syncthreads();
#pragma unroll
        for (int i = 0; i < 32; i++) {
            int cl = warp * 32 + i;
            float4 v = *(float4*)&staged[cl * STG_S + lane * 4];
            *(float4*)(out + (size_t)(rowB0 + cl) * NROWS + rowA0 + lane * 4) = v;
        }
    }
#undef ISSUE
#undef LOAD_FRAGS
#undef MMA_STEP
}

// ---------------------------------------------------------------------------
extern "C" void kernel_launch(void* const* d_in, const int* in_sizes, int n_in,
                              void* d_out, int out_size) {
    const float* f = (const float*)d_in[0];
    float* out = (float*)d_out;
    (void)in_sizes; (void)n_in; (void)out_size;

    cudaFuncSetAttribute(gemm_kernel, cudaFuncAttributeMaxDynamicSharedMemorySize, SMEM_BYTES);

    prep_kernel<<<NROWS / 8, 256>>>(f);
    gemm_kernel<<<NTILES, 128, SMEM_BYTES>>>(out);
}

// round 14
// speedup vs baseline: 2.0438x; 1.0908x over previous
#include <cuda_runtime.h>
#include <cuda_bf16.h>
#include <cstdint>

// out[i][j] = -sqrt(max(||f_i||^2 + ||f_j||^2 - 2 f_i.f_j, 0)),  f: [8192,512] fp32
// bf16 mma.sync m16n8k16 syrk, upper-triangular CTA tiles + mirrored write.
// CTA tile 128x128, 4 warps (2x2), warp tile 64x64, BK=64, 3-stage cp.async
// pipeline, 2 CTAs/SM, cross-kt fragment prefetch (barrier hidden in ks=3).
// Epilogue: shuffle-vectorized STG.128 direct stores + sqrt.approx; mirror via
// transposed SMEM staging + float4. Diagonal tiles mapped last. Diag = 0.

#define NROWS 8192
#define DDIM  512

#define TM 128
#define TN 128
#define BK 64
#define LDSZ 72                    // 64 + 8 bf16 pad -> 144B row stride, conflict-free
#define STAGES 3
#define NKT (DDIM / BK)            // 8
#define NT (NROWS / TM)            // 64
#define NSTRICT (NT * (NT - 1) / 2)   // 2016 strictly-upper tiles
#define NTILES (NSTRICT + NT)         // + 64 diagonal = 2080

#define A_ELE (TM * LDSZ)          // 9216 bf16 per stage
#define B_ELE (TN * LDSZ)
#define PIPE_BYTES (STAGES * (A_ELE + B_ELE) * 2)    // 110592 B
#define STG_S 132                  // transposed-stage stride (floats)
#define SMEM_BYTES (PIPE_BYTES + TN * 4)

__device__ __nv_bfloat16 g_fb[NROWS * DDIM];
__device__ float g_norms[NROWS];

__device__ __forceinline__ float nsqrt_approx(float x) {
    float r;
    asm("sqrt.approx.f32 %0, %1;" : "=f"(r) : "f"(x));
    return -r;
}

// ---------------------------------------------------------------------------
__global__ __launch_bounds__(512)
void prep_kernel(const float* __restrict__ f) {
    const int lane = threadIdx.x & 31;
    const int row  = blockIdx.x * 16 + (threadIdx.x >> 5);
    const float* src = f + (size_t)row * DDIM;
    __nv_bfloat16* dst = g_fb + (size_t)row * DDIM;

    float s = 0.f;
#pragma unroll
    for (int half = 0; half < 2; half++) {
        const float4 v0 = *(const float4*)(src + half * 256 + lane * 8);
        const float4 v1 = *(const float4*)(src + half * 256 + lane * 8 + 4);
        s += v0.x * v0.x + v0.y * v0.y + v0.z * v0.z + v0.w * v0.w;
        s += v1.x * v1.x + v1.y * v1.y + v1.z * v1.z + v1.w * v1.w;
        __nv_bfloat162 p0 = __float22bfloat162_rn(make_float2(v0.x, v0.y));
        __nv_bfloat162 p1 = __float22bfloat162_rn(make_float2(v0.z, v0.w));
        __nv_bfloat162 p2 = __float22bfloat162_rn(make_float2(v1.x, v1.y));
        __nv_bfloat162 p3 = __float22bfloat162_rn(make_float2(v1.z, v1.w));
        uint4 pk;
        pk.x = *(uint32_t*)&p0; pk.y = *(uint32_t*)&p1;
        pk.z = *(uint32_t*)&p2; pk.w = *(uint32_t*)&p3;
        *(uint4*)(dst + half * 256 + lane * 8) = pk;
    }
#pragma unroll
    for (int o = 16; o; o >>= 1) s += __shfl_xor_sync(0xffffffffu, s, o);
    if (lane == 0) g_norms[row] = s;
}

// ---------------------------------------------------------------------------
__device__ __forceinline__ int s_off(int x) { return x * (2 * NT - 1 - x) / 2; }

__global__ __launch_bounds__(128, 2)
void gemm_kernel(float* __restrict__ out) {
    extern __shared__ __nv_bfloat16 sm[];
    __nv_bfloat16* As = sm;                     // [STAGES][TM][LDSZ]
    __nv_bfloat16* Bs = sm + STAGES * A_ELE;    // [STAGES][TN][LDSZ]
    float* nb_s = reinterpret_cast<float*>(sm + STAGES * (A_ELE + B_ELE)); // [TN]
    float* staged = reinterpret_cast<float*>(sm);       // [TN][STG_S] (reuses pipe)

    const int tid  = threadIdx.x;
    const int lane = tid & 31;
    const int warp = tid >> 5;
    const int wm = warp >> 1;
    const int wn = warp & 1;

    // tile decode: strictly-upper first, diagonal last
    const int t = blockIdx.x;
    int bi, bj;
    if (t < NSTRICT) {
        bi = (int)(((2.f * NT - 1.f) -
                    sqrtf((2.f * NT - 1.f) * (2.f * NT - 1.f) - 8.f * (float)t)) * 0.5f);
        while (bi > 0 && s_off(bi) > t) bi--;
        while (s_off(bi + 1) <= t) bi++;
        bj = bi + 1 + (t - s_off(bi));
    } else {
        bi = bj = t - NSTRICT;
    }

    const int rowA0 = bi * TM;
    const int rowB0 = bj * TN;

    if (tid < TN) nb_s[tid] = g_norms[rowB0 + tid];

    float acc[4][8][4];
#pragma unroll
    for (int i = 0; i < 4; i++)
#pragma unroll
        for (int j = 0; j < 8; j++)
#pragma unroll
            for (int r = 0; r < 4; r++) acc[i][j][r] = 0.f;

    const int a_row = wm * 64 + (lane & 7) + ((lane >> 3) & 1) * 8;  // + mt*16
    const int a_kk  = (lane >> 4) * 8;                               // + ks*16
    const int b_row = wn * 64 + (lane & 7) + (lane >> 4) * 8;        // + p*16
    const int b_kk  = ((lane >> 3) & 1) * 8;                         // + ks*16

#define ISSUE(kt_, s_)                                                                        \
    do {                                                                                      \
        const int k0_ = (kt_) * BK;                                                           \
        __nv_bfloat16* as_ = As + (s_) * A_ELE;                                               \
        __nv_bfloat16* bs_ = Bs + (s_) * B_ELE;                                               \
        _Pragma("unroll")                                                                     \
        for (int i_ = 0; i_ < 8; i_++) {                                                      \
            int idx_ = tid + i_ * 128;                                                        \
            int r_   = idx_ >> 3;                                                             \
            int c_   = (idx_ & 7) << 3;                                                       \
            uint32_t da_ = (uint32_t)__cvta_generic_to_shared(as_ + r_ * LDSZ + c_);          \
            const __nv_bfloat16* ga_ = g_fb + (size_t)(rowA0 + r_) * DDIM + k0_ + c_;         \
            asm volatile("cp.async.cg.shared.global [%0], [%1], 16;\n" :: "r"(da_), "l"(ga_));\
            uint32_t db_ = (uint32_t)__cvta_generic_to_shared(bs_ + r_ * LDSZ + c_);          \
            const __nv_bfloat16* gb_ = g_fb + (size_t)(rowB0 + r_) * DDIM + k0_ + c_;         \
            asm volatile("cp.async.cg.shared.global [%0], [%1], 16;\n" :: "r"(db_), "l"(gb_));\
        }                                                                                     \
        asm volatile("cp.async.commit_group;\n" ::: "memory");                                \
    } while (0)

#define LOAD_FRAGS(as_, bs_, ks_, fb_)                                                        \
    do {                                                                                      \
        _Pragma("unroll")                                                                     \
        for (int mt_ = 0; mt_ < 4; mt_++) {                                                   \
            uint32_t ad_ = (uint32_t)__cvta_generic_to_shared(                                \
                (as_) + (a_row + mt_ * 16) * LDSZ + (ks_) * 16 + a_kk);                       \
            asm volatile(                                                                     \
                "ldmatrix.sync.aligned.m8n8.x4.shared.b16 {%0,%1,%2,%3}, [%4];\n"             \
                : "=r"(a[fb_][mt_][0]), "=r"(a[fb_][mt_][1]),                                 \
                  "=r"(a[fb_][mt_][2]), "=r"(a[fb_][mt_][3])                                  \
                : "r"(ad_));                                                                  \
        }                                                                                     \
        _Pragma("unroll")                                                                     \
        for (int p_ = 0; p_ < 4; p_++) {                                                      \
            uint32_t bd_ = (uint32_t)__cvta_generic_to_shared(                                \
                (bs_) + (b_row + p_ * 16) * LDSZ + (ks_) * 16 + b_kk);                        \
            asm volatile(                                                                     \
                "ldmatrix.sync.aligned.m8n8.x4.shared.b16 {%0,%1,%2,%3}, [%4];\n"             \
                : "=r"(b[fb_][2 * p_][0]), "=r"(b[fb_][2 * p_][1]),                           \
                  "=r"(b[fb_][2 * p_ + 1][0]), "=r"(b[fb_][2 * p_ + 1][1])                    \
                : "r"(bd_));                                                                  \
        }                                                                                     \
    } while (0)

#define MMA_STEP(fb_)                                                                         \
    do {                                                                                      \
        _Pragma("unroll")                                                                     \
        for (int mt_ = 0; mt_ < 4; mt_++) {                                                   \
            _Pragma("unroll")                                                                 \
            for (int nt_ = 0; nt_ < 8; nt_++) {                                               \
                asm volatile(                                                                 \
                    "mma.sync.aligned.m16n8k16.row.col.f32.bf16.bf16.f32 "                    \
                    "{%0,%1,%2,%3}, {%4,%5,%6,%7}, {%8,%9}, {%0,%1,%2,%3};\n"                 \
                    : "+f"(acc[mt_][nt_][0]), "+f"(acc[mt_][nt_][1]),                         \
                      "+f"(acc[mt_][nt_][2]), "+f"(acc[mt_][nt_][3])                          \
                    : "r"(a[fb_][mt_][0]), "r"(a[fb_][mt_][1]),                               \
                      "r"(a[fb_][mt_][2]), "r"(a[fb_][mt_][3]),                               \
                      "r"(b[fb_][nt_][0]), "r"(b[fb_][nt_][1]));                              \
            }                                                                                 \
        }                                                                                     \
    } while (0)

    uint32_t a[2][4][4];
    uint32_t b[2][8][2];

    // prologue: stage 0 ready + first fragments preloaded
    ISSUE(0, 0);
    ISSUE(1, 1);
    asm volatile("cp.async.wait_group 1;" ::: "memory");
    __syncthreads();
    {
        const __nv_bfloat16* as0 = As;
        const __nv_bfloat16* bs0 = Bs;
        LOAD_FRAGS(as0, bs0, 0, 0);
    }

    int st = 0;
    for (int kt = 0; kt < NKT; kt++) {
        if (kt + 2 < NKT) {
            int s2 = (st + 2 >= 3) ? st - 1 : st + 2;
            ISSUE(kt + 2, s2);
        }
        const __nv_bfloat16* as = As + st * A_ELE;
        const __nv_bfloat16* bs = Bs + st * B_ELE;
        const int stn = (st + 1 == 3) ? 0 : st + 1;

        LOAD_FRAGS(as, bs, 1, 1);
        MMA_STEP(0);
        LOAD_FRAGS(as, bs, 2, 0);
        MMA_STEP(1);
        LOAD_FRAGS(as, bs, 3, 1);
        MMA_STEP(0);
        if (kt + 1 < NKT) {
            if (kt + 2 < NKT)
                asm volatile("cp.async.wait_group 1;" ::: "memory");
            else
                asm volatile("cp.async.wait_group 0;" ::: "memory");
            __syncthreads();
            const __nv_bfloat16* asn = As + stn * A_ELE;
            const __nv_bfloat16* bsn = Bs + stn * B_ELE;
            LOAD_FRAGS(asn, bsn, 0, 0);
        }
        MMA_STEP(1);
        st = stn;
    }

    // ---- epilogue ---------------------------------------------------------
    const bool mirror = (bi != bj);
    const int q = lane & 3;
    const bool qeven = (q & 1) == 0;
    __syncthreads();   // all warps done with last ldmatrix; pipe smem reusable

#pragma unroll
    for (int mt = 0; mt < 4; mt++) {
        int rl0 = wm * 64 + mt * 16 + (lane >> 2);
        int rl1 = rl0 + 8;
        int r0 = rowA0 + rl0;
        int r1 = rowA0 + rl1;
        float na0 = g_norms[r0];
        float na1 = g_norms[r1];
#pragma unroll
        for (int nt = 0; nt < 8; nt++) {
            int cl = wn * 64 + nt * 8 + 2 * q;
            int c0 = rowB0 + cl;
            int c1 = c0 + 1;
            float nb0 = nb_s[cl];
            float nb1 = nb_s[cl + 1];

            float d00 = fmaxf(na0 + nb0 - 2.f * acc[mt][nt][0], 0.f);
            float d01 = fmaxf(na0 + nb1 - 2.f * acc[mt][nt][1], 0.f);
            float d10 = fmaxf(na1 + nb0 - 2.f * acc[mt][nt][2], 0.f);
            float d11 = fmaxf(na1 + nb1 - 2.f * acc[mt][nt][3], 0.f);

            float v00 = (r0 == c0) ? 0.f : nsqrt_approx(d00);
            float v01 = (r0 == c1) ? 0.f : nsqrt_approx(d01);
            float v10 = (r1 == c0) ? 0.f : nsqrt_approx(d10);
            float v11 = (r1 == c1) ? 0.f : nsqrt_approx(d11);

            // quad shuffle: even q stores r0's float4 segment, odd q stores r1's
            float x0 = __shfl_xor_sync(0xffffffffu, v00, 1);
            float x1 = __shfl_xor_sync(0xffffffffu, v01, 1);
            float y0 = __shfl_xor_sync(0xffffffffu, v10, 1);
            float y1 = __shfl_xor_sync(0xffffffffu, v11, 1);
            if (qeven) {
                // own cols 2q,2q+1 + partner cols 2q+2,2q+3 of row r0
                float4 vv = make_float4(v00, v01, x0, x1);
                *(float4*)&out[(size_t)r0 * NROWS + c0] = vv;
            } else {
                // partner cols 2q-2,2q-1 + own cols 2q,2q+1 of row r1
                float4 vv = make_float4(y0, y1, v10, v11);
                *(float4*)&out[(size_t)r1 * NROWS + (c0 - 2)] = vv;
            }

            if (mirror) {  // transposed staging: staged[cl][rl]
                staged[cl * STG_S + rl0]       = v00;
                staged[(cl + 1) * STG_S + rl0] = v01;
                staged[cl * STG_S + rl1]       = v10;
                staged[(cl + 1) * STG_S + rl1] = v11;
            }
        }
    }

    if (mirror) {
        __syncthreads();
#pragma unroll
        for (int i = 0; i < 32; i++) {
            int cl = warp * 32 + i;
            float4 v = *(float4*)&staged[cl * STG_S + lane * 4];
            *(float4*)(out + (size_t)(rowB0 + cl) * NROWS + rowA0 + lane * 4) = v;
        }
    }
#undef ISSUE
#undef LOAD_FRAGS
#undef MMA_STEP
}

// ---------------------------------------------------------------------------
extern "C" void kernel_launch(void* const* d_in, const int* in_sizes, int n_in,
                              void* d_out, int out_size) {
    const float* f = (const float*)d_in[0];
    float* out = (float*)d_out;
    (void)in_sizes; (void)n_in; (void)out_size;

    cudaFuncSetAttribute(gemm_kernel, cudaFuncAttributeMaxDynamicSharedMemorySize, SMEM_BYTES);

    prep_kernel<<<NROWS / 16, 512>>>(f);
    gemm_kernel<<<NTILES, 128, SMEM_BYTES>>>(out);
}

// round 15
// speedup vs baseline: 2.0447x; 1.0005x over previous
#include <cuda_runtime.h>
#include <cuda_fp16.h>
#include <cstdint>

// out[i][j] = -sqrt(max(||f_i||^2 + ||f_j||^2 - 2 f_i.f_j, 0)),  f: [8192,512] fp32
// fp16 mma.sync m16n8k16 (f16 accumulate = full-rate legacy HMMA) syrk,
// upper-triangular CTA tiles + mirrored write. CTA tile 128x128, 4 warps (2x2),
// warp tile 64x64, BK=64, 3-stage cp.async pipeline, 2 CTAs/SM, cross-kt
// fragment prefetch. Exact fp32 norms; fp16 gram. Shuffle-vectorized STG.128
// + sqrt.approx epilogue; mirror via transposed SMEM staging. Diag = 0.

#define NROWS 8192
#define DDIM  512

#define TM 128
#define TN 128
#define BK 64
#define LDSZ 72                    // 64 + 8 fp16 pad -> 144B row stride, conflict-free
#define STAGES 3
#define NKT (DDIM / BK)            // 8
#define NT (NROWS / TM)            // 64
#define NSTRICT (NT * (NT - 1) / 2)   // 2016 strictly-upper tiles
#define NTILES (NSTRICT + NT)         // + 64 diagonal = 2080

#define A_ELE (TM * LDSZ)          // 9216 fp16 per stage
#define B_ELE (TN * LDSZ)
#define PIPE_BYTES (STAGES * (A_ELE + B_ELE) * 2)    // 110592 B
#define STG_S 132                  // transposed-stage stride (floats)
#define SMEM_BYTES (PIPE_BYTES + TN * 4)

__device__ __half g_fb[NROWS * DDIM];
__device__ float g_norms[NROWS];

__device__ __forceinline__ float nsqrt_approx(float x) {
    float r;
    asm("sqrt.approx.f32 %0, %1;" : "=f"(r) : "f"(x));
    return -r;
}

// ---------------------------------------------------------------------------
// Prep: warp per row, float4 loads, exact fp32 norms, fp16 conversion.
// ---------------------------------------------------------------------------
__global__ __launch_bounds__(512)
void prep_kernel(const float* __restrict__ f) {
    const int lane = threadIdx.x & 31;
    const int row  = blockIdx.x * 16 + (threadIdx.x >> 5);
    const float* src = f + (size_t)row * DDIM;
    __half* dst = g_fb + (size_t)row * DDIM;

    float s = 0.f;
#pragma unroll
    for (int half = 0; half < 2; half++) {
        const float4 v0 = *(const float4*)(src + half * 256 + lane * 8);
        const float4 v1 = *(const float4*)(src + half * 256 + lane * 8 + 4);
        s += v0.x * v0.x + v0.y * v0.y + v0.z * v0.z + v0.w * v0.w;
        s += v1.x * v1.x + v1.y * v1.y + v1.z * v1.z + v1.w * v1.w;
        __half2 p0 = __float22half2_rn(make_float2(v0.x, v0.y));
        __half2 p1 = __float22half2_rn(make_float2(v0.z, v0.w));
        __half2 p2 = __float22half2_rn(make_float2(v1.x, v1.y));
        __half2 p3 = __float22half2_rn(make_float2(v1.z, v1.w));
        uint4 pk;
        pk.x = *(uint32_t*)&p0; pk.y = *(uint32_t*)&p1;
        pk.z = *(uint32_t*)&p2; pk.w = *(uint32_t*)&p3;
        *(uint4*)(dst + half * 256 + lane * 8) = pk;
    }
#pragma unroll
    for (int o = 16; o; o >>= 1) s += __shfl_xor_sync(0xffffffffu, s, o);
    if (lane == 0) g_norms[row] = s;
}

// ---------------------------------------------------------------------------
__device__ __forceinline__ int s_off(int x) { return x * (2 * NT - 1 - x) / 2; }

__global__ __launch_bounds__(128, 2)
void gemm_kernel(float* __restrict__ out) {
    extern __shared__ __half sm[];
    __half* As = sm;                     // [STAGES][TM][LDSZ]
    __half* Bs = sm + STAGES * A_ELE;    // [STAGES][TN][LDSZ]
    float* nb_s = reinterpret_cast<float*>(sm + STAGES * (A_ELE + B_ELE)); // [TN]
    float* staged = reinterpret_cast<float*>(sm);       // [TN][STG_S] (reuses pipe)

    const int tid  = threadIdx.x;
    const int lane = tid & 31;
    const int warp = tid >> 5;
    const int wm = warp >> 1;
    const int wn = warp & 1;

    // tile decode: strictly-upper first, diagonal last
    const int t = blockIdx.x;
    int bi, bj;
    if (t < NSTRICT) {
        bi = (int)(((2.f * NT - 1.f) -
                    sqrtf((2.f * NT - 1.f) * (2.f * NT - 1.f) - 8.f * (float)t)) * 0.5f);
        while (bi > 0 && s_off(bi) > t) bi--;
        while (s_off(bi + 1) <= t) bi++;
        bj = bi + 1 + (t - s_off(bi));
    } else {
        bi = bj = t - NSTRICT;
    }

    const int rowA0 = bi * TM;
    const int rowB0 = bj * TN;

    if (tid < TN) nb_s[tid] = g_norms[rowB0 + tid];

    // fp16 accumulators: 2 u32 (4 half) per (mt,nt) quad
    uint32_t acc[4][8][2];
#pragma unroll
    for (int i = 0; i < 4; i++)
#pragma unroll
        for (int j = 0; j < 8; j++) {
            acc[i][j][0] = 0u;
            acc[i][j][1] = 0u;
        }

    const int a_row = wm * 64 + (lane & 7) + ((lane >> 3) & 1) * 8;  // + mt*16
    const int a_kk  = (lane >> 4) * 8;                               // + ks*16
    const int b_row = wn * 64 + (lane & 7) + (lane >> 4) * 8;        // + p*16
    const int b_kk  = ((lane >> 3) & 1) * 8;                         // + ks*16

#define ISSUE(kt_, s_)                                                                        \
    do {                                                                                      \
        const int k0_ = (kt_) * BK;                                                           \
        __half* as_ = As + (s_) * A_ELE;                                                      \
        __half* bs_ = Bs + (s_) * B_ELE;                                                      \
        _Pragma("unroll")                                                                     \
        for (int i_ = 0; i_ < 8; i_++) {                                                      \
            int idx_ = tid + i_ * 128;                                                        \
            int r_   = idx_ >> 3;                                                             \
            int c_   = (idx_ & 7) << 3;                                                       \
            uint32_t da_ = (uint32_t)__cvta_generic_to_shared(as_ + r_ * LDSZ + c_);          \
            const __half* ga_ = g_fb + (size_t)(rowA0 + r_) * DDIM + k0_ + c_;                \
            asm volatile("cp.async.cg.shared.global [%0], [%1], 16;\n" :: "r"(da_), "l"(ga_));\
            uint32_t db_ = (uint32_t)__cvta_generic_to_shared(bs_ + r_ * LDSZ + c_);          \
            const __half* gb_ = g_fb + (size_t)(rowB0 + r_) * DDIM + k0_ + c_;                \
            asm volatile("cp.async.cg.shared.global [%0], [%1], 16;\n" :: "r"(db_), "l"(gb_));\
        }                                                                                     \
        asm volatile("cp.async.commit_group;\n" ::: "memory");                                \
    } while (0)

#define LOAD_FRAGS(as_, bs_, ks_, fb_)                                                        \
    do {                                                                                      \
        _Pragma("unroll")                                                                     \
        for (int mt_ = 0; mt_ < 4; mt_++) {                                                   \
            uint32_t ad_ = (uint32_t)__cvta_generic_to_shared(                                \
                (as_) + (a_row + mt_ * 16) * LDSZ + (ks_) * 16 + a_kk);                       \
            asm volatile(                                                                     \
                "ldmatrix.sync.aligned.m8n8.x4.shared.b16 {%0,%1,%2,%3}, [%4];\n"             \
                : "=r"(a[fb_][mt_][0]), "=r"(a[fb_][mt_][1]),                                 \
                  "=r"(a[fb_][mt_][2]), "=r"(a[fb_][mt_][3])                                  \
                : "r"(ad_));                                                                  \
        }                                                                                     \
        _Pragma("unroll")                                                                     \
        for (int p_ = 0; p_ < 4; p_++) {                                                      \
            uint32_t bd_ = (uint32_t)__cvta_generic_to_shared(                                \
                (bs_) + (b_row + p_ * 16) * LDSZ + (ks_) * 16 + b_kk);                        \
            asm volatile(                                                                     \
                "ldmatrix.sync.aligned.m8n8.x4.shared.b16 {%0,%1,%2,%3}, [%4];\n"             \
                : "=r"(b[fb_][2 * p_][0]), "=r"(b[fb_][2 * p_][1]),                           \
                  "=r"(b[fb_][2 * p_ + 1][0]), "=r"(b[fb_][2 * p_ + 1][1])                    \
                : "r"(bd_));                                                                  \
        }                                                                                     \
    } while (0)

#define MMA_STEP(fb_)                                                                         \
    do {                                                                                      \
        _Pragma("unroll")                                                                     \
        for (int mt_ = 0; mt_ < 4; mt_++) {                                                   \
            _Pragma("unroll")                                                                 \
            for (int nt_ = 0; nt_ < 8; nt_++) {                                               \
                asm volatile(                                                                 \
                    "mma.sync.aligned.m16n8k16.row.col.f16.f16.f16.f16 "                      \
                    "{%0,%1}, {%2,%3,%4,%5}, {%6,%7}, {%0,%1};\n"                             \
                    : "+r"(acc[mt_][nt_][0]), "+r"(acc[mt_][nt_][1])                          \
                    : "r"(a[fb_][mt_][0]), "r"(a[fb_][mt_][1]),                               \
                      "r"(a[fb_][mt_][2]), "r"(a[fb_][mt_][3]),                               \
                      "r"(b[fb_][nt_][0]), "r"(b[fb_][nt_][1]));                              \
            }                                                                                 \
        }                                                                                     \
    } while (0)

    uint32_t a[2][4][4];
    uint32_t b[2][8][2];

    // prologue: stage 0 ready + first fragments preloaded
    ISSUE(0, 0);
    ISSUE(1, 1);
    asm volatile("cp.async.wait_group 1;" ::: "memory");
    __syncthreads();
    {
        const __half* as0 = As;
        const __half* bs0 = Bs;
        LOAD_FRAGS(as0, bs0, 0, 0);
    }

    int st = 0;
    for (int kt = 0; kt < NKT; kt++) {
        if (kt + 2 < NKT) {
            int s2 = (st + 2 >= 3) ? st - 1 : st + 2;
            ISSUE(kt + 2, s2);
        }
        const __half* as = As + st * A_ELE;
        const __half* bs = Bs + st * B_ELE;
        const int stn = (st + 1 == 3) ? 0 : st + 1;

        LOAD_FRAGS(as, bs, 1, 1);
        MMA_STEP(0);
        LOAD_FRAGS(as, bs, 2, 0);
        MMA_STEP(1);
        LOAD_FRAGS(as, bs, 3, 1);
        MMA_STEP(0);
        if (kt + 1 < NKT) {
            if (kt + 2 < NKT)
                asm volatile("cp.async.wait_group 1;" ::: "memory");
            else
                asm volatile("cp.async.wait_group 0;" ::: "memory");
            __syncthreads();
            const __half* asn = As + stn * A_ELE;
            const __half* bsn = Bs + stn * B_ELE;
            LOAD_FRAGS(asn, bsn, 0, 0);
        }
        MMA_STEP(1);
        st = stn;
    }

    // ---- epilogue ---------------------------------------------------------
    const bool mirror = (bi != bj);
    const int q = lane & 3;
    const bool qeven = (q & 1) == 0;
    __syncthreads();   // all warps done with last ldmatrix; pipe smem reusable

#pragma unroll
    for (int mt = 0; mt < 4; mt++) {
        int rl0 = wm * 64 + mt * 16 + (lane >> 2);
        int rl1 = rl0 + 8;
        int r0 = rowA0 + rl0;
        int r1 = rowA0 + rl1;
        float na0 = g_norms[r0];
        float na1 = g_norms[r1];
#pragma unroll
        for (int nt = 0; nt < 8; nt++) {
            int cl = wn * 64 + nt * 8 + 2 * q;
            int c0 = rowB0 + cl;
            int c1 = c0 + 1;
            float nb0 = nb_s[cl];
            float nb1 = nb_s[cl + 1];

            // unpack fp16 gram: reg0 = {g(r0,c0), g(r0,c1)}, reg1 = {g(r1,c0), g(r1,c1)}
            float2 g0 = __half22float2(*(__half2*)&acc[mt][nt][0]);
            float2 g1 = __half22float2(*(__half2*)&acc[mt][nt][1]);

            float d00 = fmaxf(na0 + nb0 - 2.f * g0.x, 0.f);
            float d01 = fmaxf(na0 + nb1 - 2.f * g0.y, 0.f);
            float d10 = fmaxf(na1 + nb0 - 2.f * g1.x, 0.f);
            float d11 = fmaxf(na1 + nb1 - 2.f * g1.y, 0.f);

            float v00 = (r0 == c0) ? 0.f : nsqrt_approx(d00);
            float v01 = (r0 == c1) ? 0.f : nsqrt_approx(d01);
            float v10 = (r1 == c0) ? 0.f : nsqrt_approx(d10);
            float v11 = (r1 == c1) ? 0.f : nsqrt_approx(d11);

            // quad shuffle: even q stores r0's float4 segment, odd q stores r1's
            float x0 = __shfl_xor_sync(0xffffffffu, v00, 1);
            float x1 = __shfl_xor_sync(0xffffffffu, v01, 1);
            float y0 = __shfl_xor_sync(0xffffffffu, v10, 1);
            float y1 = __shfl_xor_sync(0xffffffffu, v11, 1);
            if (qeven) {
                float4 vv = make_float4(v00, v01, x0, x1);
                *(float4*)&out[(size_t)r0 * NROWS + c0] = vv;
            } else {
                float4 vv = make_float4(y0, y1, v10, v11);
                *(float4*)&out[(size_t)r1 * NROWS + (c0 - 2)] = vv;
            }

            if (mirror) {  // transposed staging: staged[cl][rl]
                staged[cl * STG_S + rl0]       = v00;
                staged[(cl + 1) * STG_S + rl0] = v01;
                staged[cl * STG_S + rl1]       = v10;
                staged[(cl + 1) * STG_S + rl1] = v11;
            }
        }
    }

    if (mirror) {
        __syncthreads();
#pragma unroll
        for (int i = 0; i < 32; i++) {
            int cl = warp * 32 + i;
            float4 v = *(float4*)&staged[cl * STG_S + lane * 4];
            *(float4*)(out + (size_t)(rowB0 + cl) * NROWS + rowA0 + lane * 4) = v;
        }
    }
#undef ISSUE
#undef LOAD_FRAGS
#undef MMA_STEP
}

// ---------------------------------------------------------------------------
extern "C" void kernel_launch(void* const* d_in, const int* in_sizes, int n_in,
                              void* d_out, int out_size) {
    const float* f = (const float*)d_in[0];
    float* out = (float*)d_out;
    (void)in_sizes; (void)n_in; (void)out_size;

    cudaFuncSetAttribute(gemm_kernel, cudaFuncAttributeMaxDynamicSharedMemorySize, SMEM_BYTES);

    prep_kernel<<<NROWS / 16, 512>>>(f);
    gemm_kernel<<<NTILES, 128, SMEM_BYTES>>>(out);
}

// round 16
// speedup vs baseline: 2.1086x; 1.0312x over previous
#include <cuda_runtime.h>
#include <cuda_fp16.h>
#include <cstdint>

// out[i][j] = -sqrt(max(||f_i||^2 + ||f_j||^2 - 2 f_i.f_j, 0)),  f: [8192,512] fp32
// fp16 mma.sync m16n8k16 syrk, upper-triangular CTA tiles + mirrored write.
// CTA tile 128x128, 4 warps (2x2), warp tile 64x64, BK=64, 3-stage cp.async
// pipeline, 2 CTAs/SM. FINE-GRAINED INTERLEAVE: each k16 sub-step's 8 ldmatrix
// are threaded 1-per-4-MMAs through the previous sub-step's 32 MMAs, so the
// HMMA stream never pauses for load bursts. Cross-kt barrier+prefetch kept.
// Exact fp32 norms; shuffle-vectorized STG.128 + sqrt.approx epilogue. Diag=0.

#define NROWS 8192
#define DDIM  512

#define TM 128
#define TN 128
#define BK 64
#define LDSZ 72                    // 64 + 8 fp16 pad -> 144B row stride, conflict-free
#define STAGES 3
#define NKT (DDIM / BK)            // 8
#define NT (NROWS / TM)            // 64
#define NSTRICT (NT * (NT - 1) / 2)   // 2016
#define NTILES (NSTRICT + NT)         // 2080

#define A_ELE (TM * LDSZ)          // 9216 fp16 per stage
#define B_ELE (TN * LDSZ)
#define PIPE_BYTES (STAGES * (A_ELE + B_ELE) * 2)    // 110592 B
#define STG_S 132                  // transposed-stage stride (floats)
#define SMEM_BYTES (PIPE_BYTES + TN * 4)

__device__ __half g_fb[NROWS * DDIM];
__device__ float g_norms[NROWS];

__device__ __forceinline__ float nsqrt_approx(float x) {
    float r;
    asm("sqrt.approx.f32 %0, %1;" : "=f"(r) : "f"(x));
    return -r;
}

// ---------------------------------------------------------------------------
__global__ __launch_bounds__(512)
void prep_kernel(const float* __restrict__ f) {
    const int lane = threadIdx.x & 31;
    const int row  = blockIdx.x * 16 + (threadIdx.x >> 5);
    const float* src = f + (size_t)row * DDIM;
    __half* dst = g_fb + (size_t)row * DDIM;

    float s = 0.f;
#pragma unroll
    for (int half = 0; half < 2; half++) {
        const float4 v0 = *(const float4*)(src + half * 256 + lane * 8);
        const float4 v1 = *(const float4*)(src + half * 256 + lane * 8 + 4);
        s += v0.x * v0.x + v0.y * v0.y + v0.z * v0.z + v0.w * v0.w;
        s += v1.x * v1.x + v1.y * v1.y + v1.z * v1.z + v1.w * v1.w;
        __half2 p0 = __float22half2_rn(make_float2(v0.x, v0.y));
        __half2 p1 = __float22half2_rn(make_float2(v0.z, v0.w));
        __half2 p2 = __float22half2_rn(make_float2(v1.x, v1.y));
        __half2 p3 = __float22half2_rn(make_float2(v1.z, v1.w));
        uint4 pk;
        pk.x = *(uint32_t*)&p0; pk.y = *(uint32_t*)&p1;
        pk.z = *(uint32_t*)&p2; pk.w = *(uint32_t*)&p3;
        *(uint4*)(dst + half * 256 + lane * 8) = pk;
    }
#pragma unroll
    for (int o = 16; o; o >>= 1) s += __shfl_xor_sync(0xffffffffu, s, o);
    if (lane == 0) g_norms[row] = s;
}

// ---------------------------------------------------------------------------
__device__ __forceinline__ int s_off(int x) { return x * (2 * NT - 1 - x) / 2; }

__global__ __launch_bounds__(128, 2)
void gemm_kernel(float* __restrict__ out) {
    extern __shared__ __half sm[];
    __half* As = sm;                     // [STAGES][TM][LDSZ]
    __half* Bs = sm + STAGES * A_ELE;    // [STAGES][TN][LDSZ]
    float* nb_s = reinterpret_cast<float*>(sm + STAGES * (A_ELE + B_ELE)); // [TN]
    float* staged = reinterpret_cast<float*>(sm);       // [TN][STG_S] (reuses pipe)

    const int tid  = threadIdx.x;
    const int lane = tid & 31;
    const int warp = tid >> 5;
    const int wm = warp >> 1;
    const int wn = warp & 1;

    // tile decode: strictly-upper first, diagonal last
    const int t = blockIdx.x;
    int bi, bj;
    if (t < NSTRICT) {
        bi = (int)(((2.f * NT - 1.f) -
                    sqrtf((2.f * NT - 1.f) * (2.f * NT - 1.f) - 8.f * (float)t)) * 0.5f);
        while (bi > 0 && s_off(bi) > t) bi--;
        while (s_off(bi + 1) <= t) bi++;
        bj = bi + 1 + (t - s_off(bi));
    } else {
        bi = bj = t - NSTRICT;
    }

    const int rowA0 = bi * TM;
    const int rowB0 = bj * TN;

    if (tid < TN) nb_s[tid] = g_norms[rowB0 + tid];

    // fp16 accumulators: 2 u32 (4 half) per (mt,nt)
    uint32_t acc[4][8][2];
#pragma unroll
    for (int i = 0; i < 4; i++)
#pragma unroll
        for (int j = 0; j < 8; j++) {
            acc[i][j][0] = 0u;
            acc[i][j][1] = 0u;
        }

    const int a_row = wm * 64 + (lane & 7) + ((lane >> 3) & 1) * 8;  // + mt*16
    const int a_kk  = (lane >> 4) * 8;                               // + ks*16
    const int b_row = wn * 64 + (lane & 7) + (lane >> 4) * 8;        // + p*16
    const int b_kk  = ((lane >> 3) & 1) * 8;                         // + ks*16

    uint32_t a[2][4][4];
    uint32_t b[2][8][2];

#define ISSUE(kt_, s_)                                                                        \
    do {                                                                                      \
        const int k0_ = (kt_) * BK;                                                           \
        __half* as_ = As + (s_) * A_ELE;                                                      \
        __half* bs_ = Bs + (s_) * B_ELE;                                                      \
        _Pragma("unroll")                                                                     \
        for (int i_ = 0; i_ < 8; i_++) {                                                      \
            int idx_ = tid + i_ * 128;                                                        \
            int r_   = idx_ >> 3;                                                             \
            int c_   = (idx_ & 7) << 3;                                                       \
            uint32_t da_ = (uint32_t)__cvta_generic_to_shared(as_ + r_ * LDSZ + c_);          \
            const __half* ga_ = g_fb + (size_t)(rowA0 + r_) * DDIM + k0_ + c_;                \
            asm volatile("cp.async.cg.shared.global [%0], [%1], 16;\n" :: "r"(da_), "l"(ga_));\
            uint32_t db_ = (uint32_t)__cvta_generic_to_shared(bs_ + r_ * LDSZ + c_);          \
            const __half* gb_ = g_fb + (size_t)(rowB0 + r_) * DDIM + k0_ + c_;                \
            asm volatile("cp.async.cg.shared.global [%0], [%1], 16;\n" :: "r"(db_), "l"(gb_));\
        }                                                                                     \
        asm volatile("cp.async.commit_group;\n" ::: "memory");                                \
    } while (0)

    // single ldmatrix: A fragment mt_ of sub-step ks_ into buffer fb_
#define LDSM_A(as_, ks_, fb_, mt_)                                                            \
    do {                                                                                      \
        uint32_t ad_ = (uint32_t)__cvta_generic_to_shared(                                    \
            (as_) + (a_row + (mt_) * 16) * LDSZ + (ks_) * 16 + a_kk);                         \
        asm volatile(                                                                         \
            "ldmatrix.sync.aligned.m8n8.x4.shared.b16 {%0,%1,%2,%3}, [%4];\n"                 \
            : "=r"(a[fb_][mt_][0]), "=r"(a[fb_][mt_][1]),                                     \
              "=r"(a[fb_][mt_][2]), "=r"(a[fb_][mt_][3])                                      \
            : "r"(ad_));                                                                      \
    } while (0)

    // single ldmatrix: B fragments 2p_, 2p_+1 of sub-step ks_ into buffer fb_
#define LDSM_B(bs_, ks_, fb_, p_)                                                             \
    do {                                                                                      \
        uint32_t bd_ = (uint32_t)__cvta_generic_to_shared(                                    \
            (bs_) + (b_row + (p_) * 16) * LDSZ + (ks_) * 16 + b_kk);                          \
        asm volatile(                                                                         \
            "ldmatrix.sync.aligned.m8n8.x4.shared.b16 {%0,%1,%2,%3}, [%4];\n"                 \
            : "=r"(b[fb_][2 * (p_)][0]), "=r"(b[fb_][2 * (p_)][1]),                           \
              "=r"(b[fb_][2 * (p_) + 1][0]), "=r"(b[fb_][2 * (p_) + 1][1])                    \
            : "r"(bd_));                                                                      \
    } while (0)

#define MMA1(fb_, mt_, nt_)                                                                   \
    asm volatile(                                                                             \
        "mma.sync.aligned.m16n8k16.row.col.f16.f16.f16.f16 "                                  \
        "{%0,%1}, {%2,%3,%4,%5}, {%6,%7}, {%0,%1};\n"                                         \
        : "+r"(acc[mt_][nt_][0]), "+r"(acc[mt_][nt_][1])                                      \
        : "r"(a[fb_][mt_][0]), "r"(a[fb_][mt_][1]),                                           \
          "r"(a[fb_][mt_][2]), "r"(a[fb_][mt_][3]),                                           \
          "r"(b[fb_][nt_][0]), "r"(b[fb_][nt_][1]))

    // 32 MMAs from buffer fbm_, with next sub-step's 8 LDSM (from asl_/bsl_,
    // sub-step ksl_, into buffer fbm_^1) interleaved one per 4 MMAs.
#define KSTEP(asl_, bsl_, ksl_, fbm_)                                                         \
    do {                                                                                      \
        _Pragma("unroll")                                                                     \
        for (int g_ = 0; g_ < 8; g_++) {                                                      \
            if (g_ < 4) LDSM_A(asl_, ksl_, (fbm_) ^ 1, g_);                                   \
            else        LDSM_B(bsl_, ksl_, (fbm_) ^ 1, g_ - 4);                               \
            _Pragma("unroll")                                                                 \
            for (int i_ = 0; i_ < 4; i_++) {                                                  \
                int m_ = g_ * 4 + i_;                                                         \
                MMA1(fbm_, m_ >> 3, m_ & 7);                                                  \
            }                                                                                 \
        }                                                                                     \
    } while (0)

#define MMA_STEP(fb_)                                                                         \
    do {                                                                                      \
        _Pragma("unroll")                                                                     \
        for (int mt_ = 0; mt_ < 4; mt_++) {                                                   \
            _Pragma("unroll")                                                                 \
            for (int nt_ = 0; nt_ < 8; nt_++) MMA1(fb_, mt_, nt_);                            \
        }                                                                                     \
    } while (0)

    // prologue: stage 0 ready + first fragments preloaded
    ISSUE(0, 0);
    ISSUE(1, 1);
    asm volatile("cp.async.wait_group 1;" ::: "memory");
    __syncthreads();
    {
        const __half* as0 = As;
        const __half* bs0 = Bs;
#pragma unroll
        for (int g = 0; g < 4; g++) LDSM_A(as0, 0, 0, g);
#pragma unroll
        for (int g = 0; g < 4; g++) LDSM_B(bs0, 0, 0, g);
    }

    int st = 0;
    for (int kt = 0; kt < NKT; kt++) {
        if (kt + 2 < NKT) {
            int s2 = (st + 2 >= 3) ? st - 1 : st + 2;
            ISSUE(kt + 2, s2);
        }
        const __half* as = As + st * A_ELE;
        const __half* bs = Bs + st * B_ELE;
        const int stn = (st + 1 == 3) ? 0 : st + 1;

        KSTEP(as, bs, 1, 0);   // mma ks0 (buf0), load ks1 -> buf1
        KSTEP(as, bs, 2, 1);   // mma ks1 (buf1), load ks2 -> buf0
        KSTEP(as, bs, 3, 0);   // mma ks2 (buf0), load ks3 -> buf1
        if (kt + 1 < NKT) {
            if (kt + 2 < NKT)
                asm volatile("cp.async.wait_group 1;" ::: "memory");
            else
                asm volatile("cp.async.wait_group 0;" ::: "memory");
            __syncthreads();
            const __half* asn = As + stn * A_ELE;
            const __half* bsn = Bs + stn * B_ELE;
            KSTEP(asn, bsn, 0, 1);   // mma ks3 (buf1), load next-kt ks0 -> buf0
        } else {
            MMA_STEP(1);             // last kt: plain final batch
        }
        st = stn;
    }

    // ---- epilogue ---------------------------------------------------------
    const bool mirror = (bi != bj);
    const int q = lane & 3;
    const bool qeven = (q & 1) == 0;
    __syncthreads();   // pipe smem reusable

#pragma unroll
    for (int mt = 0; mt < 4; mt++) {
        int rl0 = wm * 64 + mt * 16 + (lane >> 2);
        int rl1 = rl0 + 8;
        int r0 = rowA0 + rl0;
        int r1 = rowA0 + rl1;
        float na0 = g_norms[r0];
        float na1 = g_norms[r1];
#pragma unroll
        for (int nt = 0; nt < 8; nt++) {
            int cl = wn * 64 + nt * 8 + 2 * q;
            int c0 = rowB0 + cl;
            int c1 = c0 + 1;
            float nb0 = nb_s[cl];
            float nb1 = nb_s[cl + 1];

            float2 g0 = __half22float2(*(__half2*)&acc[mt][nt][0]);
            float2 g1 = __half22float2(*(__half2*)&acc[mt][nt][1]);

            float d00 = fmaxf(na0 + nb0 - 2.f * g0.x, 0.f);
            float d01 = fmaxf(na0 + nb1 - 2.f * g0.y, 0.f);
            float d10 = fmaxf(na1 + nb0 - 2.f * g1.x, 0.f);
            float d11 = fmaxf(na1 + nb1 - 2.f * g1.y, 0.f);

            float v00 = (r0 == c0) ? 0.f : nsqrt_approx(d00);
            float v01 = (r0 == c1) ? 0.f : nsqrt_approx(d01);
            float v10 = (r1 == c0) ? 0.f : nsqrt_approx(d10);
            float v11 = (r1 == c1) ? 0.f : nsqrt_approx(d11);

            float x0 = __shfl_xor_sync(0xffffffffu, v00, 1);
            float x1 = __shfl_xor_sync(0xffffffffu, v01, 1);
            float y0 = __shfl_xor_sync(0xffffffffu, v10, 1);
            float y1 = __shfl_xor_sync(0xffffffffu, v11, 1);
            if (qeven) {
                float4 vv = make_float4(v00, v01, x0, x1);
                *(float4*)&out[(size_t)r0 * NROWS + c0] = vv;
            } else {
                float4 vv = make_float4(y0, y1, v10, v11);
                *(float4*)&out[(size_t)r1 * NROWS + (c0 - 2)] = vv;
            }

            if (mirror) {  // transposed staging
                staged[cl * STG_S + rl0]       = v00;
                staged[(cl + 1) * STG_S + rl0] = v01;
                staged[cl * STG_S + rl1]       = v10;
                staged[(cl + 1) * STG_S + rl1] = v11;
            }
        }
    }

    if (mirror) {
        __syncthreads();
#pragma unroll
        for (int i = 0; i < 32; i++) {
            int cl = warp * 32 + i;
            float4 v = *(float4*)&staged[cl * STG_S + lane * 4];
            *(float4*)(out + (size_t)(rowB0 + cl) * NROWS + rowA0 + lane * 4) = v;
        }
    }
#undef ISSUE
#undef LDSM_A
#undef LDSM_B
#undef MMA1
#undef KSTEP
#undef MMA_STEP
}

// ---------------------------------------------------------------------------
extern "C" void kernel_launch(void* const* d_in, const int* in_sizes, int n_in,
                              void* d_out, int out_size) {
    const float* f = (const float*)d_in[0];
    float* out = (float*)d_out;
    (void)in_sizes; (void)n_in; (void)out_size;

    cudaFuncSetAttribute(gemm_kernel, cudaFuncAttributeMaxDynamicSharedMemorySize, SMEM_BYTES);

    prep_kernel<<<NROWS / 16, 512>>>(f);
    gemm_kernel<<<NTILES, 128, SMEM_BYTES>>>(out);
}